// round 15
// baseline (speedup 1.0000x reference)
#include <cuda_runtime.h>
#include <cuda_fp16.h>
#include <math.h>
#include <stdint.h>

#define D_MODEL 1024
#define NHEADS  16
#define HDIM    64
#define BATCH   2
#define SEQ     2048
#define MROWS   (BATCH*SEQ)   // 4096
#define PLN     (MROWS*D_MODEL)

// ---------------- device scratch ----------------
__device__ __align__(128) float g_sums[4];
__device__ __align__(128) __half g_Wh[4][D_MODEL*D_MODEL];
__device__ __align__(128) __half g_Xh[3][PLN];
__device__ __align__(128) __half g_Xl[3][PLN];   // lo planes (z=2 unused)
__device__ __align__(128) __half g_Qh[PLN];      // pre-scaled by 0.125*log2(e)
__device__ __align__(128) __half g_Ql[PLN];
__device__ __align__(128) __half g_Kh[PLN];
__device__ __align__(128) __half g_Kl[PLN];
__device__ __align__(128) __half g_Vh[PLN];
__device__ __align__(128) __half g_Oh[PLN];      // attention out, single fp16

#define QSCALE 0.18033688011112042f   // 0.125 * log2(e)

// ---------------- helpers ----------------
__device__ __forceinline__ void mma_f16(float* c,
    uint32_t a0, uint32_t a1, uint32_t a2, uint32_t a3,
    uint32_t b0, uint32_t b1)
{
    asm volatile(
        "mma.sync.aligned.m16n8k16.row.col.f32.f16.f16.f32 "
        "{%0,%1,%2,%3}, {%4,%5,%6,%7}, {%8,%9}, {%0,%1,%2,%3};"
        : "+f"(c[0]), "+f"(c[1]), "+f"(c[2]), "+f"(c[3])
        : "r"(a0), "r"(a1), "r"(a2), "r"(a3), "r"(b0), "r"(b1));
}

__device__ __forceinline__ void split2x(float x, float y, uint32_t& hp, uint32_t& lp) {
    __half hx = __float2half_rn(x);
    __half hy = __float2half_rn(y);
    __half lx = __float2half_rn(x - __half2float(hx));
    __half ly = __float2half_rn(y - __half2float(hy));
    __half2 h2 = __halves2half2(hx, hy);
    __half2 l2 = __halves2half2(lx, ly);
    hp = *reinterpret_cast<uint32_t*>(&h2);
    lp = *reinterpret_cast<uint32_t*>(&l2);
}
__device__ __forceinline__ uint32_t pack_h2(float x, float y) {
    __half2 t = __floats2half2_rn(x, y);
    return *reinterpret_cast<uint32_t*>(&t);
}

__device__ __forceinline__ void cpa16(uint32_t dst, const void* src) {
    asm volatile("cp.async.cg.shared.global [%0], [%1], 16;" :: "r"(dst), "l"(src));
}
#define CPA_COMMIT() asm volatile("cp.async.commit_group;" ::: "memory")
#define CPA_WAIT1()  asm volatile("cp.async.wait_group 1;" ::: "memory")

// ---------------- ternarize ----------------
__global__ void zero_sums_kernel() {
    if (threadIdx.x < 4) g_sums[threadIdx.x] = 0.0f;
}

__global__ __launch_bounds__(256) void abssum_kernel(
    const float* __restrict__ w0, const float* __restrict__ w1,
    const float* __restrict__ w2, const float* __restrict__ w3)
{
    const float* w = (blockIdx.y == 0) ? w0 : (blockIdx.y == 1) ? w1
                     : (blockIdx.y == 2) ? w2 : w3;
    const int n = D_MODEL * D_MODEL;
    float s = 0.0f;
    for (int i = blockIdx.x * blockDim.x + threadIdx.x; i < n;
         i += gridDim.x * blockDim.x)
        s += fabsf(w[i]);
    __shared__ float red[256];
    red[threadIdx.x] = s;
    __syncthreads();
    for (int o = 128; o > 0; o >>= 1) {
        if (threadIdx.x < o) red[threadIdx.x] += red[threadIdx.x + o];
        __syncthreads();
    }
    if (threadIdx.x == 0) atomicAdd(&g_sums[blockIdx.y], red[0]);
}

__global__ __launch_bounds__(256) void ternarize_kernel(
    const float* __restrict__ w0, const float* __restrict__ w1,
    const float* __restrict__ w2, const float* __restrict__ w3)
{
    const int m = blockIdx.y;
    const float* w = (m == 0) ? w0 : (m == 1) ? w1 : (m == 2) ? w2 : w3;
    const float mean = g_sums[m] * (1.0f / (float)(D_MODEL * D_MODEL));
    int i = blockIdx.x * blockDim.x + threadIdx.x;
    float v = w[i];
    float t = (fabsf(v) > mean) ? (v > 0.0f ? 1.0f : -1.0f) : 0.0f;
    g_Wh[m][i] = __float2half_rn(t);
}

// ---------------- pre-split inputs (V: hi plane only) ----------------
__global__ __launch_bounds__(256) void presplit_kernel(
    const float* __restrict__ q, const float* __restrict__ k,
    const float* __restrict__ v)
{
    const int z = blockIdx.y;
    const float* src = (z == 0) ? q : (z == 1) ? k : v;
    __half* hP = g_Xh[z];
    __half* lP = g_Xl[z];
    const int i = (blockIdx.x * blockDim.x + threadIdx.x) * 4;
    float4 val = *(const float4*)(src + i);
    uint32_t h0, l0, h1, l1;
    split2x(val.x, val.y, h0, l0);
    split2x(val.z, val.w, h1, l1);
    *(uint32_t*)(hP + i)     = h0;
    *(uint32_t*)(hP + i + 2) = h1;
    if (z < 2) {
        *(uint32_t*)(lP + i)     = l0;
        *(uint32_t*)(lP + i + 2) = l1;
    }
}

// ---------------- GEMM: 3-stage cp.async pipeline, 1-or-2-term A ----------------
#define GBM 128
#define GBN 128
#define GBK 32
#define SRH 40
#define NCH (D_MODEL/GBK)
#define GPL (GBM*SRH*2)        // 10240 (plane bytes)
#define GST (3*GPL)            // 30720 (stage bytes)
#define NSTG 3
#define GEMM_SMEM (NSTG*GST)   // 92160

__global__ __launch_bounds__(256, 2) void gemm_h2_kernel(float* __restrict__ outF, int which)
{
    extern __shared__ char gsm[];
    const uint32_t smb = (uint32_t)__cvta_generic_to_shared(gsm);

    const int tid  = threadIdx.x;
    const int lane = tid & 31;
    const int wid  = tid >> 5;
    const int wm   = wid & 1;
    const int wn   = wid >> 1;
    const int g    = lane >> 2;
    const int tig  = lane & 3;

    const int z  = blockIdx.z;
    const __half *Ah_, *Al_, *W_;
    if (which == 0) {
        Ah_ = g_Xh[z]; Al_ = g_Xl[z]; W_ = g_Wh[z];
    } else {
        Ah_ = g_Oh; Al_ = g_Oh; W_ = g_Wh[3];
    }
    const int terms = (which == 1 || z == 2) ? 1 : 2;

    const int bm = blockIdx.y * GBM;
    const int bn = blockIdx.x * GBN;

    const int lr = tid >> 1;
    const int lk = (tid & 1) * 16;
    const __half* AhP = Ah_ + (size_t)(bm + lr) * D_MODEL + lk;
    const __half* AlP = Al_ + (size_t)(bm + lr) * D_MODEL + lk;
    const __half* WP  = W_  + (size_t)(bn + lr) * D_MODEL + lk;
    const int soff = lr * (SRH * 2) + lk * 2;   // bytes; 16B aligned (80*lr + {0,32})

    float acc[4][4][4];
#pragma unroll
    for (int mf = 0; mf < 4; mf++)
#pragma unroll
        for (int nf = 0; nf < 4; nf++)
#pragma unroll
            for (int r = 0; r < 4; r++) acc[mf][nf][r] = 0.0f;

    // prologue: stages 0 and 1 in flight
#pragma unroll
    for (int p = 0; p < 2; p++) {
        const int ko = p * GBK;
        const uint32_t base = smb + p * GST;
        cpa16(base + 0 * GPL + soff,      AhP + ko);
        cpa16(base + 0 * GPL + soff + 16, AhP + ko + 8);
        if (terms == 2) {
            cpa16(base + 1 * GPL + soff,      AlP + ko);
            cpa16(base + 1 * GPL + soff + 16, AlP + ko + 8);
        }
        cpa16(base + 2 * GPL + soff,      WP + ko);
        cpa16(base + 2 * GPL + soff + 16, WP + ko + 8);
        CPA_COMMIT();
    }

    for (int c = 0; c < NCH; c++) {
        CPA_WAIT1();           // stage c's copies (this thread) complete
        __syncthreads();       // publish across block; also: all done computing c-1

        // issue chunk c+2 into stage (c+2)%3 (that stage held chunk c-1, now free)
        if (c + 2 < NCH) {
            const int ko = (c + 2) * GBK;
            const uint32_t base = smb + ((c + 2) % NSTG) * GST;
            cpa16(base + 0 * GPL + soff,      AhP + ko);
            cpa16(base + 0 * GPL + soff + 16, AhP + ko + 8);
            if (terms == 2) {
                cpa16(base + 1 * GPL + soff,      AlP + ko);
                cpa16(base + 1 * GPL + soff + 16, AlP + ko + 8);
            }
            cpa16(base + 2 * GPL + soff,      WP + ko);
            cpa16(base + 2 * GPL + soff + 16, WP + ko + 8);
        }
        CPA_COMMIT();          // commit every iteration to keep group accounting uniform

        const char* st = gsm + (c % NSTG) * GST;
#pragma unroll
        for (int s = 0; s < 2; s++) {
            uint32_t bf[4][2];
#pragma unroll
            for (int nf = 0; nf < 4; nf++) {
                const int n = wn * 32 + nf * 8 + g;
                const uint32_t* bp = (const uint32_t*)(st + 2 * GPL + n * SRH * 2) + s * 8 + tig;
                bf[nf][0] = bp[0];
                bf[nf][1] = bp[4];
            }
#pragma unroll
            for (int mf = 0; mf < 4; mf++) {
                const int m = wm * 64 + mf * 16;
                const uint32_t* ah0p = (const uint32_t*)(st + 0 * GPL + (m + g) * SRH * 2) + s * 8 + tig;
                const uint32_t* ah1p = (const uint32_t*)(st + 0 * GPL + (m + g + 8) * SRH * 2) + s * 8 + tig;
                uint32_t h0 = ah0p[0], h2 = ah0p[4];
                uint32_t h1 = ah1p[0], h3 = ah1p[4];
                if (terms == 2) {
                    const uint32_t* al0p = (const uint32_t*)(st + 1 * GPL + (m + g) * SRH * 2) + s * 8 + tig;
                    const uint32_t* al1p = (const uint32_t*)(st + 1 * GPL + (m + g + 8) * SRH * 2) + s * 8 + tig;
                    uint32_t l0 = al0p[0], l2 = al0p[4];
                    uint32_t l1 = al1p[0], l3 = al1p[4];
#pragma unroll
                    for (int nf = 0; nf < 4; nf++)
                        mma_f16(acc[mf][nf], l0, l1, l2, l3, bf[nf][0], bf[nf][1]);
                }
#pragma unroll
                for (int nf = 0; nf < 4; nf++)
                    mma_f16(acc[mf][nf], h0, h1, h2, h3, bf[nf][0], bf[nf][1]);
            }
        }
    }

    const int mode = (which == 1) ? 2 : (z == 2) ? 1 : 0;
    const float scale = (which == 0 && z == 0) ? QSCALE : 1.0f;
    __half* oh = nullptr;
    __half* ol = nullptr;
    if (which == 0) {
        if (z == 0)      { oh = g_Qh; ol = g_Ql; }
        else if (z == 1) { oh = g_Kh; ol = g_Kl; }
        else             { oh = g_Vh; }
    }

#pragma unroll
    for (int mf = 0; mf < 4; mf++) {
        const int row = bm + wm * 64 + mf * 16 + g;
#pragma unroll
        for (int nf = 0; nf < 4; nf++) {
            const int col = bn + wn * 32 + nf * 8 + tig * 2;
            if (mode == 2) {
                *(float2*)&outF[(size_t)row * D_MODEL + col] =
                    make_float2(acc[mf][nf][0], acc[mf][nf][1]);
                *(float2*)&outF[(size_t)(row + 8) * D_MODEL + col] =
                    make_float2(acc[mf][nf][2], acc[mf][nf][3]);
            } else if (mode == 0) {
                uint32_t hp, lp;
                split2x(acc[mf][nf][0] * scale, acc[mf][nf][1] * scale, hp, lp);
                *(uint32_t*)(oh + (size_t)row * D_MODEL + col) = hp;
                *(uint32_t*)(ol + (size_t)row * D_MODEL + col) = lp;
                split2x(acc[mf][nf][2] * scale, acc[mf][nf][3] * scale, hp, lp);
                *(uint32_t*)(oh + (size_t)(row + 8) * D_MODEL + col) = hp;
                *(uint32_t*)(ol + (size_t)(row + 8) * D_MODEL + col) = lp;
            } else {
                *(uint32_t*)(oh + (size_t)row * D_MODEL + col) =
                    pack_h2(acc[mf][nf][0], acc[mf][nf][1]);
                *(uint32_t*)(oh + (size_t)(row + 8) * D_MODEL + col) =
                    pack_h2(acc[mf][nf][2], acc[mf][nf][3]);
            }
        }
    }
}

// ---------------- flash: 4 warps x 32 q-rows, single-plane O output ----------------
#define FQT 128
#define FKT 64
#define NT  (SEQ/FKT)
#define ROWB 144
#define QH_OFF 0
#define QL_OFF (128*ROWB)
#define ST_OFF (2*128*ROWB)      // 36864
#define ST_SZ  (3*64*ROWB)       // 27648
#define FLASH_SMEM (ST_OFF + 2*ST_SZ)   // 92160 -> 2 blocks/SM

__global__ __launch_bounds__(128, 2) void flash_h5_kernel()
{
    extern __shared__ char fsm[];

    const int tid  = threadIdx.x;      // 0..127
    const int lane = tid & 31;
    const int wid  = tid >> 5;         // 0..3
    const int g    = lane >> 2;
    const int tig  = lane & 3;

    const int qb = blockIdx.x;
    const int h  = blockIdx.y;
    const int b  = blockIdx.z;
    const size_t qrow0 = (size_t)b * SEQ + (size_t)qb * FQT;
    const int col0 = h * HDIM;

    {
        const __half* sh = g_Qh + (qrow0 + tid) * D_MODEL + col0;
        const __half* sl = g_Ql + (qrow0 + tid) * D_MODEL + col0;
        uint4* dh = (uint4*)(fsm + QH_OFF + tid * ROWB);
        uint4* dl = (uint4*)(fsm + QL_OFF + tid * ROWB);
#pragma unroll
        for (int p = 0; p < 8; p++) {
            dh[p] = *(const uint4*)(sh + 8 * p);
            dl[p] = *(const uint4*)(sl + 8 * p);
        }
    }

    const int wb = wid * 32;

    const int keyK = tid >> 1;
    const int d0K  = (tid & 1) * 32;
    const int keyV = tid & 63;
    const int d0V  = (tid >> 6) * 32;
    const size_t kvbase = (size_t)b * SEQ * D_MODEL + col0;

    float o_acc[2][8][4];
#pragma unroll
    for (int mf = 0; mf < 2; mf++)
#pragma unroll
        for (int nf = 0; nf < 8; nf++)
#pragma unroll
            for (int r = 0; r < 4; r++) o_acc[mf][nf][r] = 0.0f;
    float m_[2][2], l_[2][2];
#pragma unroll
    for (int mf = 0; mf < 2; mf++) {
        m_[mf][0] = -INFINITY; m_[mf][1] = -INFINITY;
        l_[mf][0] = 0.0f;      l_[mf][1] = 0.0f;
    }

    uint4 kh[4], kl[4], vv[4];
    {
        const size_t sk = kvbase + (size_t)keyK * D_MODEL + d0K;
#pragma unroll
        for (int j = 0; j < 4; j++) {
            kh[j] = *(const uint4*)(g_Kh + sk + 8 * j);
            kl[j] = *(const uint4*)(g_Kl + sk + 8 * j);
        }
        const size_t sv = kvbase + (size_t)keyV * D_MODEL + d0V;
#pragma unroll
        for (int j = 0; j < 4; j++)
            vv[j] = *(const uint4*)(g_Vh + sv + 8 * j);
    }
    {
        char* st = fsm + ST_OFF;
        uint4* khp = (uint4*)(st + keyK * ROWB + d0K * 2);
        uint4* klp = (uint4*)(st + 64 * ROWB + keyK * ROWB + d0K * 2);
#pragma unroll
        for (int j = 0; j < 4; j++) { khp[j] = kh[j]; klp[j] = kl[j]; }
        char* vt = st + 128 * ROWB;
#pragma unroll
        for (int q = 0; q < 4; q++) {
            const __half* vh = (const __half*)&vv[q];
#pragma unroll
            for (int j = 0; j < 8; j++)
                *(__half*)(vt + (d0V + 8 * q + j) * ROWB + keyV * 2) = vh[j];
        }
    }
    __syncthreads();

    for (int kb = 0; kb < NT; kb++) {
        const char* st = fsm + ST_OFF + (kb & 1) * ST_SZ;

        if (kb + 1 < NT) {
            const size_t sk = kvbase + ((size_t)(kb + 1) * FKT + keyK) * D_MODEL + d0K;
#pragma unroll
            for (int j = 0; j < 4; j++) {
                kh[j] = *(const uint4*)(g_Kh + sk + 8 * j);
                kl[j] = *(const uint4*)(g_Kl + sk + 8 * j);
            }
            const size_t sv = kvbase + ((size_t)(kb + 1) * FKT + keyV) * D_MODEL + d0V;
#pragma unroll
            for (int j = 0; j < 4; j++)
                vv[j] = *(const uint4*)(g_Vh + sv + 8 * j);
        }

        float s_acc[2][8][4];
#pragma unroll
        for (int mf = 0; mf < 2; mf++)
#pragma unroll
            for (int nf = 0; nf < 8; nf++)
#pragma unroll
                for (int r = 0; r < 4; r++) s_acc[mf][nf][r] = 0.0f;

#pragma unroll
        for (int s = 0; s < 4; s++) {
            uint32_t qa[2][8];
#pragma unroll
            for (int mf = 0; mf < 2; mf++) {
                const int rA = wb + mf * 16 + g;
                const uint32_t* qh0p = (const uint32_t*)(fsm + QH_OFF + rA * ROWB) + s * 8 + tig;
                const uint32_t* qh1p = (const uint32_t*)(fsm + QH_OFF + (rA + 8) * ROWB) + s * 8 + tig;
                const uint32_t* ql0p = (const uint32_t*)(fsm + QL_OFF + rA * ROWB) + s * 8 + tig;
                const uint32_t* ql1p = (const uint32_t*)(fsm + QL_OFF + (rA + 8) * ROWB) + s * 8 + tig;
                qa[mf][0] = qh0p[0]; qa[mf][2] = qh0p[4];
                qa[mf][1] = qh1p[0]; qa[mf][3] = qh1p[4];
                qa[mf][4] = ql0p[0]; qa[mf][6] = ql0p[4];
                qa[mf][5] = ql1p[0]; qa[mf][7] = ql1p[4];
            }
#pragma unroll
            for (int nf = 0; nf < 8; nf++) {
                const uint32_t* khp = (const uint32_t*)(st + (nf * 8 + g) * ROWB) + s * 8 + tig;
                const uint32_t* klp = (const uint32_t*)(st + 64 * ROWB + (nf * 8 + g) * ROWB) + s * 8 + tig;
                uint32_t bh0 = khp[0], bh1 = khp[4];
                uint32_t bl0 = klp[0], bl1 = klp[4];
#pragma unroll
                for (int mf = 0; mf < 2; mf++) {
                    mma_f16(s_acc[mf][nf], qa[mf][0], qa[mf][1], qa[mf][2], qa[mf][3], bh0, bh1);
                    mma_f16(s_acc[mf][nf], qa[mf][4], qa[mf][5], qa[mf][6], qa[mf][7], bh0, bh1);
                    mma_f16(s_acc[mf][nf], qa[mf][0], qa[mf][1], qa[mf][2], qa[mf][3], bl0, bl1);
                }
            }
        }

#pragma unroll
        for (int mf = 0; mf < 2; mf++) {
            float mx0 = m_[mf][0], mx1 = m_[mf][1];
#pragma unroll
            for (int nf = 0; nf < 8; nf++) {
                mx0 = fmaxf(mx0, fmaxf(s_acc[mf][nf][0], s_acc[mf][nf][1]));
                mx1 = fmaxf(mx1, fmaxf(s_acc[mf][nf][2], s_acc[mf][nf][3]));
            }
            mx0 = fmaxf(mx0, __shfl_xor_sync(0xffffffff, mx0, 1));
            mx0 = fmaxf(mx0, __shfl_xor_sync(0xffffffff, mx0, 2));
            mx1 = fmaxf(mx1, __shfl_xor_sync(0xffffffff, mx1, 1));
            mx1 = fmaxf(mx1, __shfl_xor_sync(0xffffffff, mx1, 2));
            float sc0 = exp2f(m_[mf][0] - mx0);
            float sc1 = exp2f(m_[mf][1] - mx1);
            m_[mf][0] = mx0; m_[mf][1] = mx1;
            float sum0 = 0.0f, sum1 = 0.0f;
#pragma unroll
            for (int nf = 0; nf < 8; nf++) {
                s_acc[mf][nf][0] = exp2f(s_acc[mf][nf][0] - mx0);
                s_acc[mf][nf][1] = exp2f(s_acc[mf][nf][1] - mx0);
                s_acc[mf][nf][2] = exp2f(s_acc[mf][nf][2] - mx1);
                s_acc[mf][nf][3] = exp2f(s_acc[mf][nf][3] - mx1);
                sum0 += s_acc[mf][nf][0] + s_acc[mf][nf][1];
                sum1 += s_acc[mf][nf][2] + s_acc[mf][nf][3];
            }
            sum0 += __shfl_xor_sync(0xffffffff, sum0, 1);
            sum0 += __shfl_xor_sync(0xffffffff, sum0, 2);
            sum1 += __shfl_xor_sync(0xffffffff, sum1, 1);
            sum1 += __shfl_xor_sync(0xffffffff, sum1, 2);
            l_[mf][0] = l_[mf][0] * sc0 + sum0;
            l_[mf][1] = l_[mf][1] * sc1 + sum1;
#pragma unroll
            for (int nf = 0; nf < 8; nf++) {
                o_acc[mf][nf][0] *= sc0; o_acc[mf][nf][1] *= sc0;
                o_acc[mf][nf][2] *= sc1; o_acc[mf][nf][3] *= sc1;
            }
        }

#pragma unroll
        for (int s = 0; s < 4; s++) {
            uint32_t pa[2][4];
#pragma unroll
            for (int mf = 0; mf < 2; mf++) {
                pa[mf][0] = pack_h2(s_acc[mf][2 * s][0],     s_acc[mf][2 * s][1]);
                pa[mf][1] = pack_h2(s_acc[mf][2 * s][2],     s_acc[mf][2 * s][3]);
                pa[mf][2] = pack_h2(s_acc[mf][2 * s + 1][0], s_acc[mf][2 * s + 1][1]);
                pa[mf][3] = pack_h2(s_acc[mf][2 * s + 1][2], s_acc[mf][2 * s + 1][3]);
            }
#pragma unroll
            for (int nf = 0; nf < 8; nf++) {
                const uint32_t* vp = (const uint32_t*)(st + 128 * ROWB + (nf * 8 + g) * ROWB) + s * 8 + tig;
                uint32_t b0 = vp[0], b1 = vp[4];
#pragma unroll
                for (int mf = 0; mf < 2; mf++)
                    mma_f16(o_acc[mf][nf], pa[mf][0], pa[mf][1], pa[mf][2], pa[mf][3], b0, b1);
            }
        }

        if (kb + 1 < NT) {
            char* nst = fsm + ST_OFF + ((kb + 1) & 1) * ST_SZ;
            uint4* khp = (uint4*)(nst + keyK * ROWB + d0K * 2);
            uint4* klp = (uint4*)(nst + 64 * ROWB + keyK * ROWB + d0K * 2);
#pragma unroll
            for (int j = 0; j < 4; j++) { khp[j] = kh[j]; klp[j] = kl[j]; }
            char* vt = nst + 128 * ROWB;
#pragma unroll
            for (int q = 0; q < 4; q++) {
                const __half* vh = (const __half*)&vv[q];
#pragma unroll
                for (int j = 0; j < 8; j++)
                    *(__half*)(vt + (d0V + 8 * q + j) * ROWB + keyV * 2) = vh[j];
            }
        }
        __syncthreads();
    }

#pragma unroll
    for (int mf = 0; mf < 2; mf++) {
        const int rA = wb + mf * 16 + g;
        const float inv0 = 1.0f / l_[mf][0];
        const float inv1 = 1.0f / l_[mf][1];
#pragma unroll
        for (int nf = 0; nf < 8; nf++) {
            const int col = col0 + nf * 8 + tig * 2;
            *(uint32_t*)(g_Oh + (qrow0 + rA) * D_MODEL + col) =
                pack_h2(o_acc[mf][nf][0] * inv0, o_acc[mf][nf][1] * inv0);
            *(uint32_t*)(g_Oh + (qrow0 + rA + 8) * D_MODEL + col) =
                pack_h2(o_acc[mf][nf][2] * inv1, o_acc[mf][nf][3] * inv1);
        }
    }
}

// ---------------- host launch ----------------
extern "C" void kernel_launch(void* const* d_in, const int* in_sizes, int n_in,
                              void* d_out, int out_size)
{
    const float* query = (const float*)d_in[0];
    const float* key   = (const float*)d_in[1];
    const float* value = (const float*)d_in[2];
    const float* w_q   = (const float*)d_in[3];
    const float* w_k   = (const float*)d_in[4];
    const float* w_v   = (const float*)d_in[5];
    const float* w_o   = (const float*)d_in[6];
    float* out = (float*)d_out;

    cudaFuncSetAttribute(flash_h5_kernel,
                         cudaFuncAttributeMaxDynamicSharedMemorySize, FLASH_SMEM);
    cudaFuncSetAttribute(gemm_h2_kernel,
                         cudaFuncAttributeMaxDynamicSharedMemorySize, GEMM_SMEM);

    zero_sums_kernel<<<1, 32>>>();
    abssum_kernel<<<dim3(128, 4), 256>>>(w_q, w_k, w_v, w_o);
    ternarize_kernel<<<dim3(D_MODEL * D_MODEL / 256, 4), 256>>>(w_q, w_k, w_v, w_o);

    presplit_kernel<<<dim3(PLN / 1024, 3), 256>>>(query, key, value);

    gemm_h2_kernel<<<dim3(D_MODEL / GBN, MROWS / GBM, 3), 256, GEMM_SMEM>>>(nullptr, 0);

    flash_h5_kernel<<<dim3(SEQ / FQT, NHEADS, BATCH), 128, FLASH_SMEM>>>();

    gemm_h2_kernel<<<dim3(D_MODEL / GBN, MROWS / GBM, 1), 256, GEMM_SMEM>>>(out, 1);
}

// round 16
// speedup vs baseline: 1.0462x; 1.0462x over previous
#include <cuda_runtime.h>
#include <cuda_fp16.h>
#include <math.h>
#include <stdint.h>

#define D_MODEL 1024
#define NHEADS  16
#define HDIM    64
#define BATCH   2
#define SEQ     2048
#define MROWS   (BATCH*SEQ)   // 4096
#define PLN     (MROWS*D_MODEL)

// ---------------- device scratch ----------------
__device__ __align__(128) float g_sums[4];
__device__ __align__(128) __half g_Wh[4][D_MODEL*D_MODEL];
__device__ __align__(128) __half g_Xh[3][PLN];
__device__ __align__(128) __half g_Xl[3][PLN];   // lo planes (z=2 unused)
__device__ __align__(128) __half g_Qh[PLN];      // pre-scaled by 0.125*log2(e)
__device__ __align__(128) __half g_Ql[PLN];
__device__ __align__(128) __half g_Kh[PLN];
__device__ __align__(128) __half g_Kl[PLN];
__device__ __align__(128) __half g_Vh[PLN];
__device__ __align__(128) __half g_Oh[PLN];      // attention out, single fp16

#define QSCALE 0.18033688011112042f   // 0.125 * log2(e)

// ---------------- helpers ----------------
__device__ __forceinline__ void mma_f16(float* c,
    uint32_t a0, uint32_t a1, uint32_t a2, uint32_t a3,
    uint32_t b0, uint32_t b1)
{
    asm volatile(
        "mma.sync.aligned.m16n8k16.row.col.f32.f16.f16.f32 "
        "{%0,%1,%2,%3}, {%4,%5,%6,%7}, {%8,%9}, {%0,%1,%2,%3};"
        : "+f"(c[0]), "+f"(c[1]), "+f"(c[2]), "+f"(c[3])
        : "r"(a0), "r"(a1), "r"(a2), "r"(a3), "r"(b0), "r"(b1));
}

__device__ __forceinline__ void split2x(float x, float y, uint32_t& hp, uint32_t& lp) {
    __half hx = __float2half_rn(x);
    __half hy = __float2half_rn(y);
    __half lx = __float2half_rn(x - __half2float(hx));
    __half ly = __float2half_rn(y - __half2float(hy));
    __half2 h2 = __halves2half2(hx, hy);
    __half2 l2 = __halves2half2(lx, ly);
    hp = *reinterpret_cast<uint32_t*>(&h2);
    lp = *reinterpret_cast<uint32_t*>(&l2);
}
__device__ __forceinline__ uint32_t pack_h2(float x, float y) {
    __half2 t = __floats2half2_rn(x, y);
    return *reinterpret_cast<uint32_t*>(&t);
}

// ---------------- ternarize ----------------
__global__ void zero_sums_kernel() {
    if (threadIdx.x < 4) g_sums[threadIdx.x] = 0.0f;
}

__global__ __launch_bounds__(256) void abssum_kernel(
    const float* __restrict__ w0, const float* __restrict__ w1,
    const float* __restrict__ w2, const float* __restrict__ w3)
{
    const float* w = (blockIdx.y == 0) ? w0 : (blockIdx.y == 1) ? w1
                     : (blockIdx.y == 2) ? w2 : w3;
    const int n4 = D_MODEL * D_MODEL / 4;
    float s = 0.0f;
    for (int i = blockIdx.x * blockDim.x + threadIdx.x; i < n4;
         i += gridDim.x * blockDim.x) {
        float4 v = *(const float4*)(w + i * 4);
        s += fabsf(v.x) + fabsf(v.y) + fabsf(v.z) + fabsf(v.w);
    }
    __shared__ float red[256];
    red[threadIdx.x] = s;
    __syncthreads();
    for (int o = 128; o > 0; o >>= 1) {
        if (threadIdx.x < o) red[threadIdx.x] += red[threadIdx.x + o];
        __syncthreads();
    }
    if (threadIdx.x == 0) atomicAdd(&g_sums[blockIdx.y], red[0]);
}

__global__ __launch_bounds__(256) void ternarize_kernel(
    const float* __restrict__ w0, const float* __restrict__ w1,
    const float* __restrict__ w2, const float* __restrict__ w3)
{
    const int m = blockIdx.y;
    const float* w = (m == 0) ? w0 : (m == 1) ? w1 : (m == 2) ? w2 : w3;
    const float mean = g_sums[m] * (1.0f / (float)(D_MODEL * D_MODEL));
    const int i = (blockIdx.x * blockDim.x + threadIdx.x) * 4;
    float4 v = *(const float4*)(w + i);
    float t0 = (fabsf(v.x) > mean) ? (v.x > 0.0f ? 1.0f : -1.0f) : 0.0f;
    float t1 = (fabsf(v.y) > mean) ? (v.y > 0.0f ? 1.0f : -1.0f) : 0.0f;
    float t2 = (fabsf(v.z) > mean) ? (v.z > 0.0f ? 1.0f : -1.0f) : 0.0f;
    float t3 = (fabsf(v.w) > mean) ? (v.w > 0.0f ? 1.0f : -1.0f) : 0.0f;
    *(uint32_t*)(g_Wh[m] + i)     = pack_h2(t0, t1);
    *(uint32_t*)(g_Wh[m] + i + 2) = pack_h2(t2, t3);
}

// ---------------- pre-split inputs (V: hi plane only) ----------------
__global__ __launch_bounds__(256) void presplit_kernel(
    const float* __restrict__ q, const float* __restrict__ k,
    const float* __restrict__ v)
{
    const int z = blockIdx.y;
    const float* src = (z == 0) ? q : (z == 1) ? k : v;
    __half* hP = g_Xh[z];
    __half* lP = g_Xl[z];
    const int i = (blockIdx.x * blockDim.x + threadIdx.x) * 4;
    float4 val = *(const float4*)(src + i);
    uint32_t h0, l0, h1, l1;
    split2x(val.x, val.y, h0, l0);
    split2x(val.z, val.w, h1, l1);
    *(uint32_t*)(hP + i)     = h0;
    *(uint32_t*)(hP + i + 2) = h1;
    if (z < 2) {
        *(uint32_t*)(lP + i)     = l0;
        *(uint32_t*)(lP + i + 2) = l1;
    }
}

// ---------------- GEMM: double-buffered (register prefetch), 1-or-2-term A ----------------
#define GBM 128
#define GBN 128
#define GBK 32
#define SRH 40
#define NCH (D_MODEL/GBK)
#define GPL (GBM*SRH*2)        // 10240
#define GST (3*GPL)            // 30720
#define GEMM_SMEM (2*GST)      // 61440

__global__ __launch_bounds__(256, 2) void gemm_h2_kernel(float* __restrict__ outF, int which)
{
    extern __shared__ char gsm[];

    const int tid  = threadIdx.x;
    const int lane = tid & 31;
    const int wid  = tid >> 5;
    const int wm   = wid & 1;
    const int wn   = wid >> 1;
    const int g    = lane >> 2;
    const int tig  = lane & 3;

    const int z  = blockIdx.z;
    const __half *Ah_, *Al_, *W_;
    if (which == 0) {
        Ah_ = g_Xh[z]; Al_ = g_Xl[z]; W_ = g_Wh[z];
    } else {
        Ah_ = g_Oh; Al_ = g_Oh; W_ = g_Wh[3];
    }
    const int terms = (which == 1 || z == 2) ? 1 : 2;

    const int bm = blockIdx.y * GBM;
    const int bn = blockIdx.x * GBN;

    const int lr = tid >> 1;
    const int lk = (tid & 1) * 16;
    const __half* AhP = Ah_ + (size_t)(bm + lr) * D_MODEL + lk;
    const __half* AlP = Al_ + (size_t)(bm + lr) * D_MODEL + lk;
    const __half* WP  = W_  + (size_t)(bn + lr) * D_MODEL + lk;
    const int soff = lr * (SRH * 2) + lk * 2;

    float acc[4][4][4];
#pragma unroll
    for (int mf = 0; mf < 4; mf++)
#pragma unroll
        for (int nf = 0; nf < 4; nf++)
#pragma unroll
            for (int r = 0; r < 4; r++) acc[mf][nf][r] = 0.0f;

    uint4 pah0 = *(const uint4*)(AhP);
    uint4 pah1 = *(const uint4*)(AhP + 8);
    uint4 pal0, pal1;
    if (terms == 2) {
        pal0 = *(const uint4*)(AlP);
        pal1 = *(const uint4*)(AlP + 8);
    }
    uint4 pb0  = *(const uint4*)(WP);
    uint4 pb1  = *(const uint4*)(WP + 8);
    {
        uint4* dh = (uint4*)(gsm + 0 * GST + 0 * GPL + soff);
        uint4* db = (uint4*)(gsm + 0 * GST + 2 * GPL + soff);
        dh[0] = pah0; dh[1] = pah1;
        db[0] = pb0;  db[1] = pb1;
        if (terms == 2) {
            uint4* dl = (uint4*)(gsm + 0 * GST + 1 * GPL + soff);
            dl[0] = pal0; dl[1] = pal1;
        }
    }
    __syncthreads();

    for (int c = 0; c < NCH; c++) {
        const char* st = gsm + (c & 1) * GST;

        if (c + 1 < NCH) {
            const int ko = (c + 1) * GBK;
            pah0 = *(const uint4*)(AhP + ko);
            pah1 = *(const uint4*)(AhP + ko + 8);
            if (terms == 2) {
                pal0 = *(const uint4*)(AlP + ko);
                pal1 = *(const uint4*)(AlP + ko + 8);
            }
            pb0  = *(const uint4*)(WP + ko);
            pb1  = *(const uint4*)(WP + ko + 8);
        }

#pragma unroll
        for (int s = 0; s < 2; s++) {
            uint32_t bf[4][2];
#pragma unroll
            for (int nf = 0; nf < 4; nf++) {
                const int n = wn * 32 + nf * 8 + g;
                const uint32_t* bp = (const uint32_t*)(st + 2 * GPL + n * SRH * 2) + s * 8 + tig;
                bf[nf][0] = bp[0];
                bf[nf][1] = bp[4];
            }
#pragma unroll
            for (int mf = 0; mf < 4; mf++) {
                const int m = wm * 64 + mf * 16;
                const uint32_t* ah0p = (const uint32_t*)(st + 0 * GPL + (m + g) * SRH * 2) + s * 8 + tig;
                const uint32_t* ah1p = (const uint32_t*)(st + 0 * GPL + (m + g + 8) * SRH * 2) + s * 8 + tig;
                uint32_t h0 = ah0p[0], h2 = ah0p[4];
                uint32_t h1 = ah1p[0], h3 = ah1p[4];
                if (terms == 2) {
                    const uint32_t* al0p = (const uint32_t*)(st + 1 * GPL + (m + g) * SRH * 2) + s * 8 + tig;
                    const uint32_t* al1p = (const uint32_t*)(st + 1 * GPL + (m + g + 8) * SRH * 2) + s * 8 + tig;
                    uint32_t l0 = al0p[0], l2 = al0p[4];
                    uint32_t l1 = al1p[0], l3 = al1p[4];
#pragma unroll
                    for (int nf = 0; nf < 4; nf++)
                        mma_f16(acc[mf][nf], l0, l1, l2, l3, bf[nf][0], bf[nf][1]);
                }
#pragma unroll
                for (int nf = 0; nf < 4; nf++)
                    mma_f16(acc[mf][nf], h0, h1, h2, h3, bf[nf][0], bf[nf][1]);
            }
        }

        if (c + 1 < NCH) {
            char* nst = gsm + ((c + 1) & 1) * GST;
            uint4* dh = (uint4*)(nst + 0 * GPL + soff);
            uint4* db = (uint4*)(nst + 2 * GPL + soff);
            dh[0] = pah0; dh[1] = pah1;
            db[0] = pb0;  db[1] = pb1;
            if (terms == 2) {
                uint4* dl = (uint4*)(nst + 1 * GPL + soff);
                dl[0] = pal0; dl[1] = pal1;
            }
        }
        __syncthreads();
    }

    const int mode = (which == 1) ? 2 : (z == 2) ? 1 : 0;
    const float scale = (which == 0 && z == 0) ? QSCALE : 1.0f;
    __half* oh = nullptr;
    __half* ol = nullptr;
    if (which == 0) {
        if (z == 0)      { oh = g_Qh; ol = g_Ql; }
        else if (z == 1) { oh = g_Kh; ol = g_Kl; }
        else             { oh = g_Vh; }
    }

#pragma unroll
    for (int mf = 0; mf < 4; mf++) {
        const int row = bm + wm * 64 + mf * 16 + g;
#pragma unroll
        for (int nf = 0; nf < 4; nf++) {
            const int col = bn + wn * 32 + nf * 8 + tig * 2;
            if (mode == 2) {
                *(float2*)&outF[(size_t)row * D_MODEL + col] =
                    make_float2(acc[mf][nf][0], acc[mf][nf][1]);
                *(float2*)&outF[(size_t)(row + 8) * D_MODEL + col] =
                    make_float2(acc[mf][nf][2], acc[mf][nf][3]);
            } else if (mode == 0) {
                uint32_t hp, lp;
                split2x(acc[mf][nf][0] * scale, acc[mf][nf][1] * scale, hp, lp);
                *(uint32_t*)(oh + (size_t)row * D_MODEL + col) = hp;
                *(uint32_t*)(ol + (size_t)row * D_MODEL + col) = lp;
                split2x(acc[mf][nf][2] * scale, acc[mf][nf][3] * scale, hp, lp);
                *(uint32_t*)(oh + (size_t)(row + 8) * D_MODEL + col) = hp;
                *(uint32_t*)(ol + (size_t)(row + 8) * D_MODEL + col) = lp;
            } else {
                *(uint32_t*)(oh + (size_t)row * D_MODEL + col) =
                    pack_h2(acc[mf][nf][0], acc[mf][nf][1]);
                *(uint32_t*)(oh + (size_t)(row + 8) * D_MODEL + col) =
                    pack_h2(acc[mf][nf][2], acc[mf][nf][3]);
            }
        }
    }
}

// ---------------- flash: 4 warps x 32 q-rows, single-plane O output ----------------
#define FQT 128
#define FKT 64
#define NT  (SEQ/FKT)
#define ROWB 144
#define QH_OFF 0
#define QL_OFF (128*ROWB)
#define ST_OFF (2*128*ROWB)      // 36864
#define ST_SZ  (3*64*ROWB)       // 27648
#define FLASH_SMEM (ST_OFF + 2*ST_SZ)   // 92160 -> 2 blocks/SM

__global__ __launch_bounds__(128, 2) void flash_h5_kernel()
{
    extern __shared__ char fsm[];

    const int tid  = threadIdx.x;      // 0..127
    const int lane = tid & 31;
    const int wid  = tid >> 5;         // 0..3
    const int g    = lane >> 2;
    const int tig  = lane & 3;

    const int qb = blockIdx.x;
    const int h  = blockIdx.y;
    const int b  = blockIdx.z;
    const size_t qrow0 = (size_t)b * SEQ + (size_t)qb * FQT;
    const int col0 = h * HDIM;

    {
        const __half* sh = g_Qh + (qrow0 + tid) * D_MODEL + col0;
        const __half* sl = g_Ql + (qrow0 + tid) * D_MODEL + col0;
        uint4* dh = (uint4*)(fsm + QH_OFF + tid * ROWB);
        uint4* dl = (uint4*)(fsm + QL_OFF + tid * ROWB);
#pragma unroll
        for (int p = 0; p < 8; p++) {
            dh[p] = *(const uint4*)(sh + 8 * p);
            dl[p] = *(const uint4*)(sl + 8 * p);
        }
    }

    const int wb = wid * 32;

    const int keyK = tid >> 1;
    const int d0K  = (tid & 1) * 32;
    const int keyV = tid & 63;
    const int d0V  = (tid >> 6) * 32;
    const size_t kvbase = (size_t)b * SEQ * D_MODEL + col0;

    float o_acc[2][8][4];
#pragma unroll
    for (int mf = 0; mf < 2; mf++)
#pragma unroll
        for (int nf = 0; nf < 8; nf++)
#pragma unroll
            for (int r = 0; r < 4; r++) o_acc[mf][nf][r] = 0.0f;
    float m_[2][2], l_[2][2];
#pragma unroll
    for (int mf = 0; mf < 2; mf++) {
        m_[mf][0] = -INFINITY; m_[mf][1] = -INFINITY;
        l_[mf][0] = 0.0f;      l_[mf][1] = 0.0f;
    }

    uint4 kh[4], kl[4], vv[4];
    {
        const size_t sk = kvbase + (size_t)keyK * D_MODEL + d0K;
#pragma unroll
        for (int j = 0; j < 4; j++) {
            kh[j] = *(const uint4*)(g_Kh + sk + 8 * j);
            kl[j] = *(const uint4*)(g_Kl + sk + 8 * j);
        }
        const size_t sv = kvbase + (size_t)keyV * D_MODEL + d0V;
#pragma unroll
        for (int j = 0; j < 4; j++)
            vv[j] = *(const uint4*)(g_Vh + sv + 8 * j);
    }
    {
        char* st = fsm + ST_OFF;
        uint4* khp = (uint4*)(st + keyK * ROWB + d0K * 2);
        uint4* klp = (uint4*)(st + 64 * ROWB + keyK * ROWB + d0K * 2);
#pragma unroll
        for (int j = 0; j < 4; j++) { khp[j] = kh[j]; klp[j] = kl[j]; }
        char* vt = st + 128 * ROWB;
#pragma unroll
        for (int q = 0; q < 4; q++) {
            const __half* vh = (const __half*)&vv[q];
#pragma unroll
            for (int j = 0; j < 8; j++)
                *(__half*)(vt + (d0V + 8 * q + j) * ROWB + keyV * 2) = vh[j];
        }
    }
    __syncthreads();

    for (int kb = 0; kb < NT; kb++) {
        const char* st = fsm + ST_OFF + (kb & 1) * ST_SZ;

        if (kb + 1 < NT) {
            const size_t sk = kvbase + ((size_t)(kb + 1) * FKT + keyK) * D_MODEL + d0K;
#pragma unroll
            for (int j = 0; j < 4; j++) {
                kh[j] = *(const uint4*)(g_Kh + sk + 8 * j);
                kl[j] = *(const uint4*)(g_Kl + sk + 8 * j);
            }
            const size_t sv = kvbase + ((size_t)(kb + 1) * FKT + keyV) * D_MODEL + d0V;
#pragma unroll
            for (int j = 0; j < 4; j++)
                vv[j] = *(const uint4*)(g_Vh + sv + 8 * j);
        }

        float s_acc[2][8][4];
#pragma unroll
        for (int mf = 0; mf < 2; mf++)
#pragma unroll
            for (int nf = 0; nf < 8; nf++)
#pragma unroll
                for (int r = 0; r < 4; r++) s_acc[mf][nf][r] = 0.0f;

#pragma unroll
        for (int s = 0; s < 4; s++) {
            uint32_t qa[2][8];
#pragma unroll
            for (int mf = 0; mf < 2; mf++) {
                const int rA = wb + mf * 16 + g;
                const uint32_t* qh0p = (const uint32_t*)(fsm + QH_OFF + rA * ROWB) + s * 8 + tig;
                const uint32_t* qh1p = (const uint32_t*)(fsm + QH_OFF + (rA + 8) * ROWB) + s * 8 + tig;
                const uint32_t* ql0p = (const uint32_t*)(fsm + QL_OFF + rA * ROWB) + s * 8 + tig;
                const uint32_t* ql1p = (const uint32_t*)(fsm + QL_OFF + (rA + 8) * ROWB) + s * 8 + tig;
                qa[mf][0] = qh0p[0]; qa[mf][2] = qh0p[4];
                qa[mf][1] = qh1p[0]; qa[mf][3] = qh1p[4];
                qa[mf][4] = ql0p[0]; qa[mf][6] = ql0p[4];
                qa[mf][5] = ql1p[0]; qa[mf][7] = ql1p[4];
            }
#pragma unroll
            for (int nf = 0; nf < 8; nf++) {
                const uint32_t* khp = (const uint32_t*)(st + (nf * 8 + g) * ROWB) + s * 8 + tig;
                const uint32_t* klp = (const uint32_t*)(st + 64 * ROWB + (nf * 8 + g) * ROWB) + s * 8 + tig;
                uint32_t bh0 = khp[0], bh1 = khp[4];
                uint32_t bl0 = klp[0], bl1 = klp[4];
#pragma unroll
                for (int mf = 0; mf < 2; mf++) {
                    mma_f16(s_acc[mf][nf], qa[mf][0], qa[mf][1], qa[mf][2], qa[mf][3], bh0, bh1);
                    mma_f16(s_acc[mf][nf], qa[mf][4], qa[mf][5], qa[mf][6], qa[mf][7], bh0, bh1);
                    mma_f16(s_acc[mf][nf], qa[mf][0], qa[mf][1], qa[mf][2], qa[mf][3], bl0, bl1);
                }
            }
        }

#pragma unroll
        for (int mf = 0; mf < 2; mf++) {
            float mx0 = m_[mf][0], mx1 = m_[mf][1];
#pragma unroll
            for (int nf = 0; nf < 8; nf++) {
                mx0 = fmaxf(mx0, fmaxf(s_acc[mf][nf][0], s_acc[mf][nf][1]));
                mx1 = fmaxf(mx1, fmaxf(s_acc[mf][nf][2], s_acc[mf][nf][3]));
            }
            mx0 = fmaxf(mx0, __shfl_xor_sync(0xffffffff, mx0, 1));
            mx0 = fmaxf(mx0, __shfl_xor_sync(0xffffffff, mx0, 2));
            mx1 = fmaxf(mx1, __shfl_xor_sync(0xffffffff, mx1, 1));
            mx1 = fmaxf(mx1, __shfl_xor_sync(0xffffffff, mx1, 2));
            float sc0 = exp2f(m_[mf][0] - mx0);
            float sc1 = exp2f(m_[mf][1] - mx1);
            m_[mf][0] = mx0; m_[mf][1] = mx1;
            float sum0 = 0.0f, sum1 = 0.0f;
#pragma unroll
            for (int nf = 0; nf < 8; nf++) {
                s_acc[mf][nf][0] = exp2f(s_acc[mf][nf][0] - mx0);
                s_acc[mf][nf][1] = exp2f(s_acc[mf][nf][1] - mx0);
                s_acc[mf][nf][2] = exp2f(s_acc[mf][nf][2] - mx1);
                s_acc[mf][nf][3] = exp2f(s_acc[mf][nf][3] - mx1);
                sum0 += s_acc[mf][nf][0] + s_acc[mf][nf][1];
                sum1 += s_acc[mf][nf][2] + s_acc[mf][nf][3];
            }
            sum0 += __shfl_xor_sync(0xffffffff, sum0, 1);
            sum0 += __shfl_xor_sync(0xffffffff, sum0, 2);
            sum1 += __shfl_xor_sync(0xffffffff, sum1, 1);
            sum1 += __shfl_xor_sync(0xffffffff, sum1, 2);
            l_[mf][0] = l_[mf][0] * sc0 + sum0;
            l_[mf][1] = l_[mf][1] * sc1 + sum1;
#pragma unroll
            for (int nf = 0; nf < 8; nf++) {
                o_acc[mf][nf][0] *= sc0; o_acc[mf][nf][1] *= sc0;
                o_acc[mf][nf][2] *= sc1; o_acc[mf][nf][3] *= sc1;
            }
        }

#pragma unroll
        for (int s = 0; s < 4; s++) {
            uint32_t pa[2][4];
#pragma unroll
            for (int mf = 0; mf < 2; mf++) {
                pa[mf][0] = pack_h2(s_acc[mf][2 * s][0],     s_acc[mf][2 * s][1]);
                pa[mf][1] = pack_h2(s_acc[mf][2 * s][2],     s_acc[mf][2 * s][3]);
                pa[mf][2] = pack_h2(s_acc[mf][2 * s + 1][0], s_acc[mf][2 * s + 1][1]);
                pa[mf][3] = pack_h2(s_acc[mf][2 * s + 1][2], s_acc[mf][2 * s + 1][3]);
            }
#pragma unroll
            for (int nf = 0; nf < 8; nf++) {
                const uint32_t* vp = (const uint32_t*)(st + 128 * ROWB + (nf * 8 + g) * ROWB) + s * 8 + tig;
                uint32_t b0 = vp[0], b1 = vp[4];
#pragma unroll
                for (int mf = 0; mf < 2; mf++)
                    mma_f16(o_acc[mf][nf], pa[mf][0], pa[mf][1], pa[mf][2], pa[mf][3], b0, b1);
            }
        }

        if (kb + 1 < NT) {
            char* nst = fsm + ST_OFF + ((kb + 1) & 1) * ST_SZ;
            uint4* khp = (uint4*)(nst + keyK * ROWB + d0K * 2);
            uint4* klp = (uint4*)(nst + 64 * ROWB + keyK * ROWB + d0K * 2);
#pragma unroll
            for (int j = 0; j < 4; j++) { khp[j] = kh[j]; klp[j] = kl[j]; }
            char* vt = nst + 128 * ROWB;
#pragma unroll
            for (int q = 0; q < 4; q++) {
                const __half* vh = (const __half*)&vv[q];
#pragma unroll
                for (int j = 0; j < 8; j++)
                    *(__half*)(vt + (d0V + 8 * q + j) * ROWB + keyV * 2) = vh[j];
            }
        }
        __syncthreads();
    }

#pragma unroll
    for (int mf = 0; mf < 2; mf++) {
        const int rA = wb + mf * 16 + g;
        const float inv0 = 1.0f / l_[mf][0];
        const float inv1 = 1.0f / l_[mf][1];
#pragma unroll
        for (int nf = 0; nf < 8; nf++) {
            const int col = col0 + nf * 8 + tig * 2;
            *(uint32_t*)(g_Oh + (qrow0 + rA) * D_MODEL + col) =
                pack_h2(o_acc[mf][nf][0] * inv0, o_acc[mf][nf][1] * inv0);
            *(uint32_t*)(g_Oh + (qrow0 + rA + 8) * D_MODEL + col) =
                pack_h2(o_acc[mf][nf][2] * inv1, o_acc[mf][nf][3] * inv1);
        }
    }
}

// ---------------- host launch ----------------
extern "C" void kernel_launch(void* const* d_in, const int* in_sizes, int n_in,
                              void* d_out, int out_size)
{
    const float* query = (const float*)d_in[0];
    const float* key   = (const float*)d_in[1];
    const float* value = (const float*)d_in[2];
    const float* w_q   = (const float*)d_in[3];
    const float* w_k   = (const float*)d_in[4];
    const float* w_v   = (const float*)d_in[5];
    const float* w_o   = (const float*)d_in[6];
    float* out = (float*)d_out;

    cudaFuncSetAttribute(flash_h5_kernel,
                         cudaFuncAttributeMaxDynamicSharedMemorySize, FLASH_SMEM);
    cudaFuncSetAttribute(gemm_h2_kernel,
                         cudaFuncAttributeMaxDynamicSharedMemorySize, GEMM_SMEM);

    zero_sums_kernel<<<1, 32>>>();
    abssum_kernel<<<dim3(64, 4), 256>>>(w_q, w_k, w_v, w_o);
    ternarize_kernel<<<dim3(D_MODEL * D_MODEL / 1024, 4), 256>>>(w_q, w_k, w_v, w_o);

    presplit_kernel<<<dim3(PLN / 1024, 3), 256>>>(query, key, value);

    gemm_h2_kernel<<<dim3(D_MODEL / GBN, MROWS / GBM, 3), 256, GEMM_SMEM>>>(nullptr, 0);

    flash_h5_kernel<<<dim3(SEQ / FQT, NHEADS, BATCH), 128, FLASH_SMEM>>>();

    gemm_h2_kernel<<<dim3(D_MODEL / GBN, MROWS / GBM, 1), 256, GEMM_SMEM>>>(out, 1);
}